// round 16
// baseline (speedup 1.0000x reference)
#include <cuda_runtime.h>
#include <cuda_fp16.h>

// E=500000, P=4000000, D=U=64.
__device__ int g_counts[500032];      // per-dst neighbor count
__device__ int g_offsets[500032];     // exclusive prefix of counts
__device__ int g_cursor[500032];      // scatter cursors
__device__ int g_src_sorted[4000000]; // src ids grouped by dst
__device__ unsigned long long g_scanState[512]; // decoupled-lookback state
__device__ __half g_xform_h[500000 * 64]; // fp16 transformed features (feat@W)

// scan state flags (high 32 bits): 1 = aggregate, 2 = inclusive prefix
#define SCAN_AGG    1u
#define SCAN_PREFIX 2u

__device__ __forceinline__ void scan_publish(unsigned long long* p,
                                             unsigned int flag, int val)
{
    unsigned long long v = ((unsigned long long)flag << 32) | (unsigned int)val;
    asm volatile("st.release.gpu.global.u64 [%0], %1;" :: "l"(p), "l"(v) : "memory");
}
__device__ __forceinline__ unsigned long long scan_peek(const unsigned long long* p)
{
    unsigned long long v;
    asm volatile("ld.acquire.gpu.global.u64 %0, [%1];" : "=l"(v) : "l"(p) : "memory");
    return v;
}

// ---------------------------------------------------------------------------
// prep: blocks [0, nXf) compute xform = fp16(feat @ W) with HMMA
// (mma.sync.m16n8k16); remaining blocks histogram dst ids. (R15 verbatim.)
// ---------------------------------------------------------------------------
__global__ void prep_kernel(const float* __restrict__ feat,
                            const float* __restrict__ W,
                            int nXf, int E,
                            const int4* __restrict__ nbr2, int P2, int P)
{
    __shared__ __half2 sWb[64 * 36];   // [n][k2]: (W[2k2][n], W[2k2+1][n])

    if ((int)blockIdx.x < nXf) {
        for (int i = threadIdx.x; i < 64 * 32; i += 256) {
            int n  = i >> 5;
            int k2 = i & 31;
            sWb[n * 36 + k2] = __floats2half2_rn(W[(2 * k2)     * 64 + n],
                                                 W[(2 * k2 + 1) * 64 + n]);
        }
        __syncthreads();

        const int warp = threadIdx.x >> 5;
        const int lane = threadIdx.x & 31;
        const int m0   = blockIdx.x * 128 + warp * 16;
        const int r    = lane >> 2;          // 0..7
        const int c2   = (lane & 3) * 2;     // 0,2,4,6
        const int rowLo = m0 + r;
        const int rowHi = m0 + r + 8;

        unsigned int afr[4][4];
        #pragma unroll
        for (int ks = 0; ks < 4; ks++) {
            const int k0 = ks * 16;
            float2 lo0 = make_float2(0.f, 0.f), hi0 = lo0, lo8 = lo0, hi8 = lo0;
            if (rowLo < E) {
                lo0 = *reinterpret_cast<const float2*>(&feat[(long)rowLo * 64 + k0 + c2]);
                lo8 = *reinterpret_cast<const float2*>(&feat[(long)rowLo * 64 + k0 + 8 + c2]);
            }
            if (rowHi < E) {
                hi0 = *reinterpret_cast<const float2*>(&feat[(long)rowHi * 64 + k0 + c2]);
                hi8 = *reinterpret_cast<const float2*>(&feat[(long)rowHi * 64 + k0 + 8 + c2]);
            }
            __half2 h;
            h = __floats2half2_rn(lo0.x, lo0.y); afr[ks][0] = *reinterpret_cast<unsigned int*>(&h);
            h = __floats2half2_rn(hi0.x, hi0.y); afr[ks][1] = *reinterpret_cast<unsigned int*>(&h);
            h = __floats2half2_rn(lo8.x, lo8.y); afr[ks][2] = *reinterpret_cast<unsigned int*>(&h);
            h = __floats2half2_rn(hi8.x, hi8.y); afr[ks][3] = *reinterpret_cast<unsigned int*>(&h);
        }

        const int bn = lane >> 2;
        const int bk = lane & 3;

        #pragma unroll
        for (int nt = 0; nt < 8; nt++) {
            const int n0 = nt * 8;
            float d0 = 0.f, d1 = 0.f, d2 = 0.f, d3 = 0.f;
            #pragma unroll
            for (int ks = 0; ks < 4; ks++) {
                const int koff2 = ks * 8;
                const __half2 hb0 = sWb[(n0 + bn) * 36 + koff2 + bk];
                const __half2 hb1 = sWb[(n0 + bn) * 36 + koff2 + 4 + bk];
                const unsigned int b0 = *reinterpret_cast<const unsigned int*>(&hb0);
                const unsigned int b1 = *reinterpret_cast<const unsigned int*>(&hb1);
                asm volatile(
                    "mma.sync.aligned.m16n8k16.row.col.f32.f16.f16.f32 "
                    "{%0,%1,%2,%3}, {%4,%5,%6,%7}, {%8,%9}, {%0,%1,%2,%3};"
                    : "+f"(d0), "+f"(d1), "+f"(d2), "+f"(d3)
                    : "r"(afr[ks][0]), "r"(afr[ks][1]),
                      "r"(afr[ks][2]), "r"(afr[ks][3]),
                      "r"(b0), "r"(b1));
            }
            if (rowLo < E)
                *reinterpret_cast<__half2*>(&g_xform_h[(long)rowLo * 64 + n0 + c2]) =
                    __floats2half2_rn(d0, d1);
            if (rowHi < E)
                *reinterpret_cast<__half2*>(&g_xform_h[(long)rowHi * 64 + n0 + c2]) =
                    __floats2half2_rn(d2, d3);
        }
    } else {
        int q = (blockIdx.x - nXf) * 256 + threadIdx.x;
        if (q >= P2) return;
        int4 e = __ldcs(&nbr2[q]);     // {dst0, src0, dst1, src1}
        atomicAdd(&g_counts[e.x], 1);
        int p1 = q * 2 + 1;
        if (p1 < P) atomicAdd(&g_counts[e.z], 1);
    }
}

// ---------------------------------------------------------------------------
// Single-kernel exclusive scan with WARP-WIDE decoupled lookback: warp 0
// peeks 32 predecessor states per round trip (vs 1 in the naive frontier).
// All <=489 blocks are co-resident (>=8 blocks/SM capacity) -> no progress
// hazard. g_scanState zeroed by memsetAsync before launch.
// ---------------------------------------------------------------------------
__global__ void scan_kernel(int E)
{
    __shared__ int s[256];
    __shared__ int sBase;

    const int tid  = threadIdx.x;
    const int bid  = blockIdx.x;
    const int base = bid * 1024 + tid * 4;

    int c[4];
    int tsum = 0;
    #pragma unroll
    for (int j = 0; j < 4; j++) {
        int idx = base + j;
        c[j] = (idx < E) ? g_counts[idx] : 0;
        tsum += c[j];
    }
    s[tid] = tsum;
    __syncthreads();
    for (int o = 1; o < 256; o <<= 1) {
        int t = (tid >= o) ? s[tid - o] : 0;
        __syncthreads();
        s[tid] += t;
        __syncthreads();
    }
    const int total = s[255];

    if (tid < 32) {
        const unsigned full = 0xFFFFFFFFu;
        if (bid == 0) {
            if (tid == 0) {
                scan_publish(&g_scanState[0], SCAN_PREFIX, total);
                sBase = 0;
            }
        } else {
            if (tid == 0) scan_publish(&g_scanState[bid], SCAN_AGG, total);
            int running = 0;
            int j = bid - 1;
            for (;;) {
                int idx = j - tid;
                unsigned long long v = (idx >= 0)
                    ? scan_peek(&g_scanState[idx])
                    : ((unsigned long long)SCAN_PREFIX << 32);  // OOB = prefix 0
                unsigned f = (unsigned)(v >> 32);
                unsigned bNone = __ballot_sync(full, f == 0u);
                if (bNone) continue;                 // someone unpublished: retry
                unsigned bPre = __ballot_sync(full, f == SCAN_PREFIX);
                int firstP = bPre ? (__ffs(bPre) - 1) : 32;
                int contrib = (tid <= firstP || firstP == 32) ? (int)(unsigned)v : 0;
                if (tid > firstP) contrib = 0;
                #pragma unroll
                for (int o = 16; o; o >>= 1)
                    contrib += __shfl_xor_sync(full, contrib, o);
                running += contrib;
                if (firstP < 32) break;
                j -= 32;
            }
            if (tid == 0) {
                scan_publish(&g_scanState[bid], SCAN_PREFIX, running + total);
                sBase = running;
            }
        }
    }
    __syncthreads();

    int run = sBase + (s[tid] - tsum);     // exclusive base for this thread
    #pragma unroll
    for (int j = 0; j < 4; j++) {
        int idx = base + j;
        if (idx < E) {
            g_offsets[idx] = run;
            g_cursor[idx]  = run;
        }
        run += c[j];
    }
}

// ---------------------------------------------------------------------------
__global__ void sort_scatter_kernel(const int4* __restrict__ nbr2, int P2, int P)
{
    int q = blockIdx.x * 256 + threadIdx.x;
    if (q >= P2) return;
    int4 e = __ldcs(&nbr2[q]);
    int pos0 = atomicAdd(&g_cursor[e.x], 1);
    g_src_sorted[pos0] = e.y;
    int p1 = q * 2 + 1;
    if (p1 < P) {
        int pos1 = atomicAdd(&g_cursor[e.z], 1);
        g_src_sorted[pos1] = e.w;
    }
}

// ---------------------------------------------------------------------------
// Aggregate kernel (R15 verbatim): out[r,:] = sum xform[s,:] + bias.
// Half-warp team per dst row, padded MLP-8 batches, fp32 accum, no smem,
// no barriers. NOW THE 4th KERNEL -> ncu capture lands here.
// ---------------------------------------------------------------------------
__global__ void __launch_bounds__(256) agg_kernel(
    const float* __restrict__ bias,   // [64]
    float* __restrict__ out,          // [E, 64]
    int E)
{
    const int tid  = threadIdx.x;
    const int row0 = blockIdx.x * 64;
    const int lane16 = tid & 15;          // column segment (4 halves = 8B)
    const int tteam  = tid >> 4;          // 0..15
    const uint2* __restrict__ fh =
        reinterpret_cast<const uint2*>(g_xform_h) + lane16;  // row stride 16
    const float4 b = *reinterpret_cast<const float4*>(&bias[lane16 * 4]);

    #pragma unroll
    for (int rr = 0; rr < 4; rr++) {
        const int lr = rr * 16 + tteam;   // local row 0..63
        const int r  = row0 + lr;
        if (r >= E) continue;

        float a0 = 0.f, a1 = 0.f, a2 = 0.f, a3 = 0.f;
        const int start = g_offsets[r];
        const int cnt   = g_counts[r];
        if (cnt > 0) {
            const int last = start + cnt - 1;
            for (int i = start; i <= last; i += 8) {
                int s_[8];
                #pragma unroll
                for (int j = 0; j < 8; j++) {
                    int idx = i + j;
                    s_[j] = __ldcs(&g_src_sorted[idx <= last ? idx : last]);
                }
                uint2 v[8];
                #pragma unroll
                for (int j = 0; j < 8; j++)
                    v[j] = fh[(long)s_[j] * 16];
                #pragma unroll
                for (int j = 0; j < 8; j++) {
                    if (i + j <= last) {
                        float2 f0 = __half22float2(*reinterpret_cast<__half2*>(&v[j].x));
                        float2 f1 = __half22float2(*reinterpret_cast<__half2*>(&v[j].y));
                        a0 += f0.x; a1 += f0.y; a2 += f1.x; a3 += f1.y;
                    }
                }
            }
        }
        float4 o;
        o.x = a0 + b.x; o.y = a1 + b.y; o.z = a2 + b.z; o.w = a3 + b.w;
        *reinterpret_cast<float4*>(&out[(long)r * 64 + lane16 * 4]) = o;
    }
}

// ---------------------------------------------------------------------------
extern "C" void kernel_launch(void* const* d_in, const int* in_sizes, int n_in,
                              void* d_out, int out_size)
{
    const float* feat = (const float*)d_in[0];   // [E, 64] f32
    const int*   nbr  = (const int*)d_in[1];     // [P, 2]  i32
    const float* W    = (const float*)d_in[2];   // [64, 64] f32
    const float* bias = (const float*)d_in[3];   // [64] f32
    float* out = (float*)d_out;                  // [E, 64] f32

    const int E = in_sizes[0] / 64;
    const int P = in_sizes[1] / 2;

    const int P2    = (P + 1) / 2;
    const int blkP2 = (P2 + 255) / 256;
    const int NB    = (E + 1023) / 1024;         // <= 512 scan blocks
    const int nXf   = (E + 127) / 128;           // HMMA transform blocks

    // zero counts + scan state (memsets; not kernel launches)
    void* counts_ptr = nullptr;
    cudaGetSymbolAddress(&counts_ptr, g_counts);
    cudaMemsetAsync(counts_ptr, 0, (size_t)E * sizeof(int), 0);
    void* state_ptr = nullptr;
    cudaGetSymbolAddress(&state_ptr, g_scanState);
    cudaMemsetAsync(state_ptr, 0, sizeof(unsigned long long) * 512, 0);

    prep_kernel<<<nXf + blkP2, 256>>>(feat, W, nXf, E,
                                      (const int4*)nbr, P2, P);   // kernel #1
    scan_kernel<<<NB, 256>>>(E);                                  // kernel #2
    sort_scatter_kernel<<<blkP2, 256>>>((const int4*)nbr, P2, P); // kernel #3
    const int blkA = (E + 63) / 64;
    agg_kernel<<<blkA, 256>>>(bias, out, E);                      // kernel #4
}